// round 1
// baseline (speedup 1.0000x reference)
#include <cuda_runtime.h>

// Composed affine map: 9 rows, each padded to 12 floats:
// [w0..w8, bias, pad, pad]
__device__ float g_aff[9 * 12];

// ---------------------------------------------------------------------------
// Kernel 1: compose the 8 conv layers into one affine map (A, v).
// Single block, 96 threads; threads 0..89 own entry (o, c) of the augmented
// 9x10 matrix M (column 9 = bias vector). Each layer applies the 3x3 conv
// (with zero padding on the 3x3 grid) to every column of M, adding b_d to
// the bias column.
// ---------------------------------------------------------------------------
__global__ void compose_kernel(const float* __restrict__ w,   // [8*9]
                               const float* __restrict__ b) { // [8]
    __shared__ float M[2][9][10];
    int t = threadIdx.x;
    int o = t / 10;   // output element index (i*3+j)
    int c = t % 10;   // column (0..8 = input elem, 9 = bias)

    if (t < 90) M[0][o][c] = (c < 9 && o == c) ? 1.0f : 0.0f;
    __syncthreads();

    int cur = 0;
    for (int d = 0; d < 8; d++) {
        float acc = 0.0f;
        if (t < 90) {
            int i = o / 3, j = o % 3;
#pragma unroll
            for (int di = -1; di <= 1; di++) {
#pragma unroll
                for (int dj = -1; dj <= 1; dj++) {
                    int ii = i + di, jj = j + dj;
                    if (ii >= 0 && ii < 3 && jj >= 0 && jj < 3) {
                        acc += w[d * 9 + (di + 1) * 3 + (dj + 1)] *
                               M[cur][ii * 3 + jj][c];
                    }
                }
            }
            if (c == 9) acc += b[d];
            M[1 ^ cur][o][c] = acc;
        }
        __syncthreads();
        cur ^= 1;
    }

    if (t < 90) g_aff[o * 12 + c] = M[cur][o][c];
    // zero the pad slots (read as float2 tail but unused values)
    if (t >= 90 && t < 108) {
        int p = t - 90;
        g_aff[(p / 2) * 12 + 10 + (p % 2)] = 0.0f;
    }
}

// ---------------------------------------------------------------------------
// Kernel 2: streaming y = A x + v, 4 rows per thread.
// Each thread: 9 x LDG.128 (144 contiguous bytes), 4 x (81 FMA) , 9 x STG.128.
// A is broadcast-loaded from __device__ global (uniform address, L1 hits).
// ---------------------------------------------------------------------------
__global__ __launch_bounds__(256)
void affine_kernel(const float* __restrict__ x,
                   float* __restrict__ out,
                   int nrows) {
    long long t  = (long long)blockIdx.x * 256 + threadIdx.x;
    long long r0 = t * 4;
    if (r0 >= nrows) return;

    if (r0 + 4 <= nrows) {
        float xr[36];
        const float4* xin = (const float4*)(x + r0 * 9);
#pragma unroll
        for (int i = 0; i < 9; i++) ((float4*)xr)[i] = xin[i];

        float y[36];
#pragma unroll
        for (int o = 0; o < 9; o++) {
            float4 a0 = *(const float4*)&g_aff[o * 12 + 0];
            float4 a1 = *(const float4*)&g_aff[o * 12 + 4];
            float2 a2 = *(const float2*)&g_aff[o * 12 + 8]; // a2.x = w8, a2.y = bias
#pragma unroll
            for (int r = 0; r < 4; r++) {
                const float* xp = xr + r * 9;
                float acc = fmaf(a0.x, xp[0], a2.y);
                acc = fmaf(a0.y, xp[1], acc);
                acc = fmaf(a0.z, xp[2], acc);
                acc = fmaf(a0.w, xp[3], acc);
                acc = fmaf(a1.x, xp[4], acc);
                acc = fmaf(a1.y, xp[5], acc);
                acc = fmaf(a1.z, xp[6], acc);
                acc = fmaf(a1.w, xp[7], acc);
                acc = fmaf(a2.x, xp[8], acc);
                y[r * 9 + o] = acc;
            }
        }

        float4* yo = (float4*)(out + r0 * 9);
#pragma unroll
        for (int i = 0; i < 9; i++) yo[i] = ((const float4*)y)[i];
    } else {
        // scalar tail (not hit for N = 4,000,000, kept for safety)
        for (long long r = r0; r < nrows; r++) {
#pragma unroll
            for (int o = 0; o < 9; o++) {
                float acc = g_aff[o * 12 + 9];
#pragma unroll
                for (int c = 0; c < 9; c++)
                    acc = fmaf(g_aff[o * 12 + c], x[r * 9 + c], acc);
                out[r * 9 + o] = acc;
            }
        }
    }
}

extern "C" void kernel_launch(void* const* d_in, const int* in_sizes, int n_in,
                              void* d_out, int out_size) {
    const float* x = (const float*)d_in[0];  // [N*9]
    const float* w = (const float*)d_in[1];  // [8*9]
    const float* b = (const float*)d_in[2];  // [8]
    float* out = (float*)d_out;              // [N*9]

    int nrows = in_sizes[0] / 9;

    compose_kernel<<<1, 96>>>(w, b);

    long long nthreads = ((long long)nrows + 3) / 4;
    int blocks = (int)((nthreads + 255) / 256);
    affine_kernel<<<blocks, 256>>>(x, out, nrows);
}